// round 3
// baseline (speedup 1.0000x reference)
#include <cuda_runtime.h>
#include <cstdint>
#include <cstddef>

// out[b,j] = in2[b,j] * sum_i in1[b,i] * (sum_k w[i,j,k])
// B=16384, I=64, J=2048, K=64.

#define B_DIM 16384
#define I_DIM 64
#define J_DIM 2048
#define K_DIM 64

#define BM 128
#define BN 128
#define AS_STRIDE 132  // floats; 16B-aligned rows, breaks the stride-128 bank pattern

// Dynamic smem: As (64*132 floats) followed by Bs (64*128 floats) = 66560 B.
#define SMEM_BYTES ((I_DIM * AS_STRIDE + I_DIM * BN) * (int)sizeof(float))

// 512 KB scratch for the K-reduced weights, [i][j] row-major.
__device__ float g_w2[I_DIM * J_DIM];

// ---------------------------------------------------------------------------
// Kernel 1: w2[i,j] = sum_k w[i,j,k].  One warp per (i,j): 64 contiguous
// floats -> 2 per lane (float2, fully coalesced 256B/warp) + shuffle reduce.
// ---------------------------------------------------------------------------
__global__ void reduce_w_kernel(const float* __restrict__ w) {
    int gwarp = (blockIdx.x * blockDim.x + threadIdx.x) >> 5;
    int lane  = threadIdx.x & 31;
    if (gwarp >= I_DIM * J_DIM) return;
    const float2* p = reinterpret_cast<const float2*>(w) + (size_t)gwarp * 32;
    float2 v = p[lane];
    float s = v.x + v.y;
    #pragma unroll
    for (int off = 16; off; off >>= 1)
        s += __shfl_xor_sync(0xffffffffu, s, off);
    if (lane == 0) g_w2[gwarp] = s;
}

// ---------------------------------------------------------------------------
// Kernel 2: 128x128 tile GEMM (K=64, single shot, no k-pipeline) with packed
// fma.rn.f32x2 accumulators along the j dimension, fused *in2 epilogue.
// Thread tile 8(b) x 8(j) = 8 x 4 f32x2 pairs.
// ---------------------------------------------------------------------------
__global__ __launch_bounds__(256, 2)
void bilinear_kernel(const float* __restrict__ in1,
                     const float* __restrict__ in2,
                     float* __restrict__ out) {
    extern __shared__ float smem[];
    float* As = smem;                          // [i][b]  64 x 132 (b minor)
    float* Bs = smem + I_DIM * AS_STRIDE;      // [i][j]  64 x 128 (j minor)

    const int t  = threadIdx.x;
    const int tx = t & 15;   // j-group 0..15
    const int ty = t >> 4;   // b-group 0..15
    const int jBase = blockIdx.x * BN;
    const int bBase = blockIdx.y * BM;

    // --- load A transposed: in1 is [b][i] (i contiguous) -> As[i][b] ---
    // Consecutive lanes read consecutive i: global coalesced; STS has a
    // bounded 4-way bank conflict (stride 132), one-time cost.
    #pragma unroll
    for (int r = 0; r < (BM * I_DIM) / 256; r++) {
        int gidx = t + r * 256;       // 0..8191
        int b = gidx >> 6;            // /64
        int i = gidx & 63;
        As[i * AS_STRIDE + b] = in1[(size_t)(bBase + b) * I_DIM + i];
    }

    // --- load Bs: g_w2[i][jBase..jBase+127], float4, fully coalesced ---
    #pragma unroll
    for (int r = 0; r < (I_DIM * BN / 4) / 256; r++) {
        int idx4 = t + r * 256;       // 0..2047
        int i  = idx4 >> 5;
        int jc = idx4 & 31;
        reinterpret_cast<float4*>(Bs)[i * (BN / 4) + jc] =
            reinterpret_cast<const float4*>(g_w2 + (size_t)i * J_DIM + jBase)[jc];
    }
    __syncthreads();

    // --- mainloop over full K depth (64) ---
    unsigned long long acc[8][4];
    #pragma unroll
    for (int m = 0; m < 8; m++)
        #pragma unroll
        for (int n = 0; n < 4; n++)
            acc[m][n] = 0ull;  // bit pattern of (0.0f, 0.0f)

    #pragma unroll 4
    for (int i = 0; i < I_DIM; i++) {
        const float4 a0 = *reinterpret_cast<const float4*>(&As[i * AS_STRIDE + ty * 4]);
        const float4 a1 = *reinterpret_cast<const float4*>(&As[i * AS_STRIDE + 64 + ty * 4]);
        const ulonglong2 b0 = *reinterpret_cast<const ulonglong2*>(&Bs[i * BN + tx * 4]);
        const ulonglong2 b1 = *reinterpret_cast<const ulonglong2*>(&Bs[i * BN + 64 + tx * 4]);

        const float av[8] = {a0.x, a0.y, a0.z, a0.w, a1.x, a1.y, a1.z, a1.w};
        const unsigned long long bv[4] = {b0.x, b0.y, b1.x, b1.y};

        #pragma unroll
        for (int m = 0; m < 8; m++) {
            unsigned long long a2;
            asm("mov.b64 %0, {%1, %1};" : "=l"(a2) : "f"(av[m]));
            #pragma unroll
            for (int n = 0; n < 4; n++) {
                asm("fma.rn.f32x2 %0, %1, %2, %0;"
                    : "+l"(acc[m][n]) : "l"(a2), "l"(bv[n]));
            }
        }
    }

    // --- epilogue: out = acc * in2, 128-bit loads/stores ---
    #pragma unroll
    for (int m = 0; m < 8; m++) {
        const int b = bBase + ((m < 4) ? (ty * 4 + m) : (64 + ty * 4 + (m - 4)));
        const size_t row = (size_t)b * J_DIM + jBase;

        {   // j group 0: cols tx*4 .. tx*4+3  -> acc[m][0], acc[m][1]
            const ulonglong2 c2 = *reinterpret_cast<const ulonglong2*>(&in2[row + tx * 4]);
            ulonglong2 o;
            asm("mul.rn.f32x2 %0, %1, %2;" : "=l"(o.x) : "l"(acc[m][0]), "l"(c2.x));
            asm("mul.rn.f32x2 %0, %1, %2;" : "=l"(o.y) : "l"(acc[m][1]), "l"(c2.y));
            *reinterpret_cast<ulonglong2*>(&out[row + tx * 4]) = o;
        }
        {   // j group 1: cols 64 + tx*4 ..   -> acc[m][2], acc[m][3]
            const ulonglong2 c2 = *reinterpret_cast<const ulonglong2*>(&in2[row + 64 + tx * 4]);
            ulonglong2 o;
            asm("mul.rn.f32x2 %0, %1, %2;" : "=l"(o.x) : "l"(acc[m][2]), "l"(c2.x));
            asm("mul.rn.f32x2 %0, %1, %2;" : "=l"(o.y) : "l"(acc[m][3]), "l"(c2.y));
            *reinterpret_cast<ulonglong2*>(&out[row + 64 + tx * 4]) = o;
        }
    }
}

// ---------------------------------------------------------------------------
extern "C" void kernel_launch(void* const* d_in, const int* in_sizes, int n_in,
                              void* d_out, int out_size) {
    (void)in_sizes; (void)n_in; (void)out_size;
    const float* in1 = (const float*)d_in[0];   // (16384, 64)
    const float* in2 = (const float*)d_in[1];   // (16384, 2048)
    const float* w   = (const float*)d_in[2];   // (64, 2048, 64)
    float* out = (float*)d_out;                 // (16384, 2048) fp32

    // Opt in to >48KB dynamic smem (host-side attribute set; not a stream op,
    // not an allocation — legal under graph capture).
    cudaFuncSetAttribute(bilinear_kernel,
                         cudaFuncAttributeMaxDynamicSharedMemorySize, SMEM_BYTES);

    // Kernel 1: 131072 warps, 8 warps/block.
    reduce_w_kernel<<<(I_DIM * J_DIM) / 8, 256>>>(w);

    // Kernel 2: 16 x 128 blocks of 256 threads.
    dim3 grid(J_DIM / BN, B_DIM / BM);
    bilinear_kernel<<<grid, 256, SMEM_BYTES>>>(in1, in2, out);
}